// round 8
// baseline (speedup 1.0000x reference)
#include <cuda_runtime.h>
#include <cuda_fp8.h>
#include <cuda_fp16.h>
#include <cstdint>

// Quantize_55327768707293
// x: [8192, 8192] fp32. Tiled 128x128. Per tile:
//   absmax -> e = ceil(log2(absmax)) (absmax==0 -> e=0)
//   scale = 2^(e-1)   (MAX_EXP = 1)
//   xq = fp32(fp8_e5m2(x * 2^(1-e)))
// Output: [xq (8192*8192 fp32) | scale (64*64 fp32)]
//
// R8: R7 (persistent 444 CTAs, register-staged tile, 3 CTAs/SM) with the
// reduction bug fixed: the all-warp final butterfly must span the FULL warp
// (offsets 16..1) because lanes 16-31 seed with 0.0f; R7's 8..1 butterfly
// left lanes 16-31 with a=0 -> wrong scale for half of each warp.

constexpr int N        = 8192;
constexpr int B        = 128;
constexpr int TILES    = N / B;          // 64
constexpr int NTILES   = TILES * TILES;  // 4096
constexpr int THREADS  = 512;            // 16 warps
constexpr int NWARPS   = THREADS / 32;
constexpr int SWEEPS   = B / NWARPS;     // 8 float4 per thread (32 floats)
constexpr int ROW4     = N / 4;
constexpr int CTAS_PER_SM = 3;
constexpr int GRID     = 148 * CTAS_PER_SM;  // 444 persistent CTAs

__device__ __forceinline__ float2 fakequant2(float a, float b) {
    // fp32 -> e5m2 (RNE, hardware cvt) -> half (exact) -> fp32 (exact)
    float2 in = make_float2(a, b);
    __nv_fp8x2_storage_t q = __nv_cvt_float2_to_fp8x2(in, __NV_SATFINITE, __NV_E5M2);
    __half2_raw hr = __nv_cvt_fp8x2_to_halfraw2(q, __NV_E5M2);
    __half2 h = *reinterpret_cast<__half2*>(&hr);
    return __half22float2(h);
}

__global__ void __launch_bounds__(THREADS, CTAS_PER_SM)
quantize_persist_kernel(const float* __restrict__ x,
                        float* __restrict__ out,
                        float* __restrict__ scale_out) {
    __shared__ float smax[NWARPS];

    const int warp = threadIdx.x >> 5;
    const int lane = threadIdx.x & 31;

    for (int t = blockIdx.x; t < NTILES; t += GRID) {
        const int ty = t >> 6, tx = t & 63;
        const size_t tile_base = (size_t)ty * B * N + (size_t)tx * B;
        const float4* __restrict__ xin = reinterpret_cast<const float4*>(x + tile_base);
        float4* __restrict__ oq        = reinterpret_cast<float4*>(out + tile_base);

        // ---- Load whole tile into registers; front-batched LDG.128 ----
        float4 v[SWEEPS];
        #pragma unroll
        for (int i = 0; i < SWEEPS; i++) {
            const int row = warp + i * NWARPS;
            v[i] = __ldcs(&xin[(size_t)row * ROW4 + lane]);
        }

        // ---- Local absmax ----
        float amax = 0.0f;
        #pragma unroll
        for (int i = 0; i < SWEEPS; i++) {
            amax = fmaxf(amax, fmaxf(fmaxf(fabsf(v[i].x), fabsf(v[i].y)),
                                     fmaxf(fabsf(v[i].z), fabsf(v[i].w))));
        }

        // ---- Block reduce absmax ----
        #pragma unroll
        for (int o = 16; o > 0; o >>= 1)
            amax = fmaxf(amax, __shfl_xor_sync(0xffffffffu, amax, o));
        if (lane == 0) smax[warp] = amax;
        __syncthreads();
        // Every warp redundantly reduces the 16 per-warp maxima. Lanes >=16
        // seed 0.0f, so the butterfly MUST span the full warp (16..1): fmaxf
        // absorbs the zero seeds and all 32 lanes converge to the block max.
        float a;
        {
            float m = (lane < NWARPS) ? smax[lane] : 0.0f;
            #pragma unroll
            for (int o = 16; o > 0; o >>= 1)
                m = fmaxf(m, __shfl_xor_sync(0xffffffffu, m, o));
            a = m;
        }
        __syncthreads();   // protect smax before next iteration's writes

        // ---- e = ceil(log2(a)), exact; a==0 -> e=0 ----
        int e = 0;
        if (a > 0.0f) {
            int k;
            float m = frexpf(a, &k);          // a = m * 2^k, m in [0.5, 1)
            e = (m == 0.5f) ? (k - 1) : k;    // exact power of two -> k-1
        }
        const float inv = ldexpf(1.0f, 1 - e);    // 2^(MAX_EXP - e), exact

        // ---- Quantize from registers, streaming stores ----
        #pragma unroll
        for (int i = 0; i < SWEEPS; i++) {
            const int row = warp + i * NWARPS;
            float2 xy = fakequant2(v[i].x * inv, v[i].y * inv);
            float2 zw = fakequant2(v[i].z * inv, v[i].w * inv);
            __stcs(&oq[(size_t)row * ROW4 + lane],
                   make_float4(xy.x, xy.y, zw.x, zw.y));
        }

        if (threadIdx.x == 0)
            scale_out[t] = ldexpf(1.0f, e - 1);
    }
}

extern "C" void kernel_launch(void* const* d_in, const int* in_sizes, int n_in,
                              void* d_out, int out_size) {
    (void)in_sizes; (void)n_in; (void)out_size;
    const float* x = (const float*)d_in[0];
    float* out = (float*)d_out;
    float* scale_out = out + (size_t)N * N;

    quantize_persist_kernel<<<GRID, THREADS>>>(x, out, scale_out);
}

// round 9
// speedup vs baseline: 1.1243x; 1.1243x over previous
#include <cuda_runtime.h>
#include <cuda_fp8.h>
#include <cuda_fp16.h>

// Quantize_55327768707293
// x: [8192, 8192] fp32. Tiled 128x128. Per tile:
//   absmax -> e = ceil(log2(absmax)) (absmax==0 -> e=0)
//   scale = 2^(e-1)   (MAX_EXP = 1)
//   xq = fp32(fp8_e5m2(x * 2^(1-e)))
// Output: [xq (8192*8192 fp32) | scale (64*64 fp32)]
//
// R9: exact R1 memory structure (the best measured: 4096 CTAs, 512 thr,
// 2 CTAs/SM, register-staged tile, plain cached ld/st — cache hints and all
// other structures measured worse across R2-R8). Single micro-trim: the
// block reduce uses ONE barrier + redundant all-warp butterfly instead of
// two barriers + smem broadcast.

constexpr int N        = 8192;
constexpr int B        = 128;
constexpr int TILES    = N / B;          // 64
constexpr int THREADS  = 512;            // 16 warps
constexpr int NWARPS   = THREADS / 32;
constexpr int SWEEPS   = B / NWARPS;     // 8 float4 per thread (32 floats)
constexpr int ROW4     = N / 4;

__device__ __forceinline__ float2 fakequant2(float a, float b) {
    // fp32 -> e5m2 (RNE, hardware cvt) -> half (exact) -> fp32 (exact)
    float2 in = make_float2(a, b);
    __nv_fp8x2_storage_t q = __nv_cvt_float2_to_fp8x2(in, __NV_SATFINITE, __NV_E5M2);
    __half2_raw hr = __nv_cvt_fp8x2_to_halfraw2(q, __NV_E5M2);
    __half2 h = *reinterpret_cast<__half2*>(&hr);
    return __half22float2(h);
}

__global__ void __launch_bounds__(THREADS, 2)
quantize_tile_kernel(const float* __restrict__ x,
                     float* __restrict__ out,
                     float* __restrict__ scale_out) {
    const int tx   = blockIdx.x;          // tile col
    const int ty   = blockIdx.y;          // tile row
    const int warp = threadIdx.x >> 5;
    const int lane = threadIdx.x & 31;

    const size_t tile_base = (size_t)ty * B * N + (size_t)tx * B;
    const float4* __restrict__ xin = reinterpret_cast<const float4*>(x + tile_base);
    float4* __restrict__ oq        = reinterpret_cast<float4*>(out + tile_base);

    // ---- Load whole tile into registers; front-batched LDG.128 for MLP ----
    float4 v[SWEEPS];
    #pragma unroll
    for (int i = 0; i < SWEEPS; i++) {
        const int row = warp + i * NWARPS;
        v[i] = xin[(size_t)row * ROW4 + lane];
    }

    // ---- Local absmax ----
    float amax = 0.0f;
    #pragma unroll
    for (int i = 0; i < SWEEPS; i++) {
        amax = fmaxf(amax, fmaxf(fmaxf(fabsf(v[i].x), fabsf(v[i].y)),
                                 fmaxf(fabsf(v[i].z), fabsf(v[i].w))));
    }

    // ---- Block reduce absmax: warp butterfly -> smem -> ONE barrier ->
    //      redundant all-warp butterfly over the 16 per-warp maxima.
    //      Lanes >=16 seed 0.0f, so the butterfly must span the FULL warp
    //      (offsets 16..1); fmaxf absorbs the zero seeds. ----
    #pragma unroll
    for (int o = 16; o > 0; o >>= 1)
        amax = fmaxf(amax, __shfl_xor_sync(0xffffffffu, amax, o));

    __shared__ float smax[NWARPS];
    if (lane == 0) smax[warp] = amax;
    __syncthreads();
    float a = (lane < NWARPS) ? smax[lane] : 0.0f;
    #pragma unroll
    for (int o = 16; o > 0; o >>= 1)
        a = fmaxf(a, __shfl_xor_sync(0xffffffffu, a, o));

    // ---- e = ceil(log2(a)), exact; a==0 -> e=0 ----
    int e = 0;
    if (a > 0.0f) {
        int k;
        float m = frexpf(a, &k);          // a = m * 2^k, m in [0.5, 1)
        e = (m == 0.5f) ? (k - 1) : k;    // exact power of two -> k-1
    }
    const float inv = ldexpf(1.0f, 1 - e);    // 2^(MAX_EXP - e), exact

    // ---- Quantize from registers, store ----
    #pragma unroll
    for (int i = 0; i < SWEEPS; i++) {
        const int row = warp + i * NWARPS;
        float2 xy = fakequant2(v[i].x * inv, v[i].y * inv);
        float2 zw = fakequant2(v[i].z * inv, v[i].w * inv);
        oq[(size_t)row * ROW4 + lane] = make_float4(xy.x, xy.y, zw.x, zw.y);
    }

    if (threadIdx.x == 0)
        scale_out[ty * TILES + tx] = ldexpf(1.0f, e - 1);
}

extern "C" void kernel_launch(void* const* d_in, const int* in_sizes, int n_in,
                              void* d_out, int out_size) {
    (void)in_sizes; (void)n_in; (void)out_size;
    const float* x = (const float*)d_in[0];
    float* out = (float*)d_out;
    float* scale_out = out + (size_t)N * N;

    dim3 grid(TILES, TILES);
    quantize_tile_kernel<<<grid, THREADS>>>(x, out, scale_out);
}